// round 4
// baseline (speedup 1.0000x reference)
#include <cuda_runtime.h>
#include <math.h>
#include <float.h>

// ---------------------------------------------------------------- constants
#define BATCH 2
#define SEQ   512
#define HID   1024
#define NHEAD 16
#define HDIM  64
#define NLAYER 4
#define FFD   4096
#define NCLS  14
#define TOK   (BATCH*SEQ)     // 1024
#define RSPAN 512             // 2*SPAN
#define ZBATCH (BATCH*NHEAD)  // 32

// ---------------------------------------------------------------- scratch
__device__ float g_x[TOK*HID];
__device__ float g_q[TOK*HID];
__device__ float g_k[TOK*HID];
__device__ float g_v[TOK*HID];
__device__ float g_ctx[TOK*HID];
__device__ float g_tmp[TOK*HID];
__device__ float g_relln[RSPAN*HID];
__device__ float g_posk[RSPAN*HID];
__device__ float g_posq[RSPAN*HID];
__device__ float g_scores[(size_t)ZBATCH*SEQ*SEQ];
__device__ float g_c2p[(size_t)ZBATCH*SEQ*RSPAN];
__device__ float g_p2c[(size_t)ZBATCH*SEQ*RSPAN];
__device__ float g_ff[(size_t)TOK*FFD];
__device__ int   g_c2pidx[SEQ*SEQ];
__device__ int   g_p2cidx[SEQ*SEQ];
__device__ float g_maskf[TOK];
__device__ float g_nll[TOK];

__device__ __forceinline__ float gelu_exact(float x) {
    return 0.5f * x * (1.0f + erff(x * 0.70710678118654752440f));
}

// ---------------------------------------------------------------- embed + LN + mask
__global__ void embed_kernel(const float* __restrict__ we, const float* __restrict__ sc,
                             const float* __restrict__ bi, const int* __restrict__ ids,
                             const int* __restrict__ att) {
    __shared__ float sm[HID];
    __shared__ float red[256];
    int t = blockIdx.x, tid = threadIdx.x;
    const float* row = we + (size_t)ids[t] * HID;
    float s1 = 0.f;
    for (int i = tid; i < HID; i += 256) { float v = row[i]; sm[i] = v; s1 += v; }
    red[tid] = s1; __syncthreads();
    for (int s = 128; s; s >>= 1) { if (tid < s) red[tid] += red[tid + s]; __syncthreads(); }
    float mu = red[0] * (1.0f / HID); __syncthreads();
    float s2 = 0.f;
    for (int i = tid; i < HID; i += 256) { float d = sm[i] - mu; s2 += d * d; }
    red[tid] = s2; __syncthreads();
    for (int s = 128; s; s >>= 1) { if (tid < s) red[tid] += red[tid + s]; __syncthreads(); }
    float inv = rsqrtf(red[0] * (1.0f / HID) + 1e-7f);
    float mf = (float)att[t];
    if (tid == 0) g_maskf[t] = mf;
    for (int i = tid; i < HID; i += 256)
        g_x[(size_t)t * HID + i] = ((sm[i] - mu) * inv * sc[i] + bi[i]) * mf;
}

// ---------------------------------------------------------------- plain row LN
__global__ void ln_kernel(const float* __restrict__ in, const float* __restrict__ sc,
                          const float* __restrict__ bi, float* __restrict__ out) {
    __shared__ float sm[HID];
    __shared__ float red[256];
    int t = blockIdx.x, tid = threadIdx.x;
    const float* row = in + (size_t)t * HID;
    float s1 = 0.f;
    for (int i = tid; i < HID; i += 256) { float v = row[i]; sm[i] = v; s1 += v; }
    red[tid] = s1; __syncthreads();
    for (int s = 128; s; s >>= 1) { if (tid < s) red[tid] += red[tid + s]; __syncthreads(); }
    float mu = red[0] * (1.0f / HID); __syncthreads();
    float s2 = 0.f;
    for (int i = tid; i < HID; i += 256) { float d = sm[i] - mu; s2 += d * d; }
    red[tid] = s2; __syncthreads();
    for (int s = 128; s; s >>= 1) { if (tid < s) red[tid] += red[tid + s]; __syncthreads(); }
    float inv = rsqrtf(red[0] * (1.0f / HID) + 1e-7f);
    for (int i = tid; i < HID; i += 256)
        out[(size_t)t * HID + i] = (sm[i] - mu) * inv * sc[i] + bi[i];
}

// ---------------------------------------------------------------- residual + LN
__global__ void add_ln_kernel(const float* __restrict__ x, const float* __restrict__ d,
                              const float* __restrict__ sc, const float* __restrict__ bi,
                              float* __restrict__ out) {
    __shared__ float sm[HID];
    __shared__ float red[256];
    int t = blockIdx.x, tid = threadIdx.x;
    float s1 = 0.f;
    for (int i = tid; i < HID; i += 256) {
        float v = x[(size_t)t * HID + i] + d[(size_t)t * HID + i];
        sm[i] = v; s1 += v;
    }
    red[tid] = s1; __syncthreads();
    for (int s = 128; s; s >>= 1) { if (tid < s) red[tid] += red[tid + s]; __syncthreads(); }
    float mu = red[0] * (1.0f / HID); __syncthreads();
    float s2 = 0.f;
    for (int i = tid; i < HID; i += 256) { float dv = sm[i] - mu; s2 += dv * dv; }
    red[tid] = s2; __syncthreads();
    for (int s = 128; s; s >>= 1) { if (tid < s) red[tid] += red[tid + s]; __syncthreads(); }
    float inv = rsqrtf(red[0] * (1.0f / HID) + 1e-7f);
    for (int i = tid; i < HID; i += 256)
        out[(size_t)t * HID + i] = (sm[i] - mu) * inv * sc[i] + bi[i];
}

// ---------------------------------------------------------------- relative-position buckets
__global__ void relidx_kernel() {
    int idx = blockIdx.x * blockDim.x + threadIdx.x;
    if (idx >= SEQ * SEQ) return;
    int i = idx >> 9, j = idx & 511;
    int rel = i - j;
    const int mid = 128;
    int apos = (rel < mid && rel > -mid) ? (mid - 1) : (rel < 0 ? -rel : rel);
    int bucket;
    if (apos <= mid) {
        bucket = rel;
    } else {
        const float LOGC = logf(511.0f / 128.0f);
        float lp = ceilf(logf((float)apos / 128.0f) / LOGC * 127.0f) + 128.0f;
        float sg = (rel > 0) ? 1.0f : ((rel < 0) ? -1.0f : 0.0f);
        bucket = (int)(lp * sg);
    }
    int c = bucket + 256;  c = c < 0 ? 0 : (c > 511 ? 511 : c);
    int p = -bucket + 256; p = p < 0 ? 0 : (p > 511 ? 511 : p);
    g_c2pidx[idx] = c;
    g_p2cidx[idx] = p;
}

// ---------------------------------------------------------------- dense GEMM  C = A@B + bias  (opt. exact gelu)
template <int ACT>
__global__ void __launch_bounds__(256) gemm_nn(const float* __restrict__ A, const float* __restrict__ B,
                                               const float* __restrict__ bias, float* __restrict__ C,
                                               int M, int N, int K) {
    __shared__ float As[16][64];
    __shared__ float Bs[16][64];
    int tid = threadIdx.x;
    int bm = blockIdx.y * 64, bn = blockIdx.x * 64;
    int tx = tid & 15, ty = tid >> 4;
    float acc[4][4] = {};
    for (int k0 = 0; k0 < K; k0 += 16) {
#pragma unroll
        for (int i = 0; i < 4; i++) {
            int e = tid + i * 256;
            int m = e >> 4, kk = e & 15;
            As[kk][m] = A[(size_t)(bm + m) * K + k0 + kk];
            int kb = e >> 6, n = e & 63;
            Bs[kb][n] = B[(size_t)(k0 + kb) * N + bn + n];
        }
        __syncthreads();
#pragma unroll
        for (int kk = 0; kk < 16; kk++) {
            float a[4], b[4];
#pragma unroll
            for (int i = 0; i < 4; i++) { a[i] = As[kk][ty * 4 + i]; b[i] = Bs[kk][tx * 4 + i]; }
#pragma unroll
            for (int i = 0; i < 4; i++)
#pragma unroll
                for (int j = 0; j < 4; j++) acc[i][j] += a[i] * b[j];
        }
        __syncthreads();
    }
#pragma unroll
    for (int i = 0; i < 4; i++)
#pragma unroll
        for (int j = 0; j < 4; j++) {
            int m = bm + ty * 4 + i, n = bn + tx * 4 + j;
            float c = acc[i][j] + bias[n];
            if (ACT) c = gelu_exact(c);
            C[(size_t)m * N + n] = c;
        }
}

// ---------------------------------------------------------------- batched NT GEMM  C = A @ B^T  (per b,h)
__global__ void __launch_bounds__(256) bgemm_nt(const float* __restrict__ A, const float* __restrict__ B,
                                                float* __restrict__ C,
                                                int M, int N, int K, int lda, int ldb, int ldc,
                                                long aB, long aH, long bB, long bH, long cZ) {
    __shared__ float As[16][64];
    __shared__ float Bs[16][64];
    int z = blockIdx.z, bb = z / NHEAD, h = z % NHEAD;
    const float* Az = A + (size_t)bb * aB + (size_t)h * aH;
    const float* Bz = B + (size_t)bb * bB + (size_t)h * bH;
    float* Cz = C + (size_t)z * cZ;
    int tid = threadIdx.x;
    int bm = blockIdx.y * 64, bn = blockIdx.x * 64;
    int tx = tid & 15, ty = tid >> 4;
    float acc[4][4] = {};
    for (int k0 = 0; k0 < K; k0 += 16) {
#pragma unroll
        for (int i = 0; i < 4; i++) {
            int e = tid + i * 256;
            int r = e >> 4, kk = e & 15;
            As[kk][r] = Az[(size_t)(bm + r) * lda + k0 + kk];
            Bs[kk][r] = Bz[(size_t)(bn + r) * ldb + k0 + kk];
        }
        __syncthreads();
#pragma unroll
        for (int kk = 0; kk < 16; kk++) {
            float a[4], b[4];
#pragma unroll
            for (int i = 0; i < 4; i++) { a[i] = As[kk][ty * 4 + i]; b[i] = Bs[kk][tx * 4 + i]; }
#pragma unroll
            for (int i = 0; i < 4; i++)
#pragma unroll
                for (int j = 0; j < 4; j++) acc[i][j] += a[i] * b[j];
        }
        __syncthreads();
    }
#pragma unroll
    for (int i = 0; i < 4; i++)
#pragma unroll
        for (int j = 0; j < 4; j++)
            Cz[(size_t)(bm + ty * 4 + i) * ldc + bn + tx * 4 + j] = acc[i][j];
}

// ---------------------------------------------------------------- batched NN GEMM (ctx = probs @ V)
__global__ void __launch_bounds__(256) bgemm_nn(const float* __restrict__ A, const float* __restrict__ B,
                                                float* __restrict__ C,
                                                int M, int N, int K, int lda, int ldb, int ldc,
                                                long aZ, long bB, long bH, long cB, long cH) {
    __shared__ float As[16][64];
    __shared__ float Bs[16][64];
    int z = blockIdx.z, bb = z / NHEAD, h = z % NHEAD;
    const float* Az = A + (size_t)z * aZ;
    const float* Bz = B + (size_t)bb * bB + (size_t)h * bH;
    float* Cz = C + (size_t)bb * cB + (size_t)h * cH;
    int tid = threadIdx.x;
    int bm = blockIdx.y * 64, bn = blockIdx.x * 64;
    int tx = tid & 15, ty = tid >> 4;
    float acc[4][4] = {};
    for (int k0 = 0; k0 < K; k0 += 16) {
#pragma unroll
        for (int i = 0; i < 4; i++) {
            int e = tid + i * 256;
            int m = e >> 4, kk = e & 15;
            As[kk][m] = Az[(size_t)(bm + m) * lda + k0 + kk];
            int kb = e >> 6, n = e & 63;
            Bs[kb][n] = Bz[(size_t)(k0 + kb) * ldb + bn + n];
        }
        __syncthreads();
#pragma unroll
        for (int kk = 0; kk < 16; kk++) {
            float a[4], b[4];
#pragma unroll
            for (int i = 0; i < 4; i++) { a[i] = As[kk][ty * 4 + i]; b[i] = Bs[kk][tx * 4 + i]; }
#pragma unroll
            for (int i = 0; i < 4; i++)
#pragma unroll
                for (int j = 0; j < 4; j++) acc[i][j] += a[i] * b[j];
        }
        __syncthreads();
    }
#pragma unroll
    for (int i = 0; i < 4; i++)
#pragma unroll
        for (int j = 0; j < 4; j++)
            Cz[(size_t)(bm + ty * 4 + i) * ldc + bn + tx * 4 + j] = acc[i][j];
}

// ---------------------------------------------------------------- combine biases + scale + mask + XSoftmax
__global__ void softmax_kernel() {
    __shared__ float red[256];
    int zq = blockIdx.x;
    int z = zq >> 9, q = zq & 511;
    int bb = z / NHEAD;
    int tid = threadIdx.x;
    const float SCALE = sqrtf(192.0f);  // sqrt(D*3)
    float mq = g_maskf[bb * SEQ + q];
    size_t rowS = ((size_t)z * SEQ + q) * SEQ;
    size_t rowC = ((size_t)z * SEQ + q) * RSPAN;

    int k0 = tid, k1 = tid + 256;
    float s0 = g_scores[rowS + k0]
             + g_c2p[rowC + g_c2pidx[q * SEQ + k0]]
             + g_p2c[((size_t)z * SEQ + k0) * RSPAN + g_p2cidx[k0 * SEQ + q]];
    float s1 = g_scores[rowS + k1]
             + g_c2p[rowC + g_c2pidx[q * SEQ + k1]]
             + g_p2c[((size_t)z * SEQ + k1) * RSPAN + g_p2cidx[k1 * SEQ + q]];
    s0 /= SCALE; s1 /= SCALE;
    bool m0 = (mq * g_maskf[bb * SEQ + k0]) > 0.f;
    bool m1 = (mq * g_maskf[bb * SEQ + k1]) > 0.f;
    float v0 = m0 ? s0 : -FLT_MAX;
    float v1 = m1 ? s1 : -FLT_MAX;

    red[tid] = fmaxf(v0, v1); __syncthreads();
    for (int s = 128; s; s >>= 1) { if (tid < s) red[tid] = fmaxf(red[tid], red[tid + s]); __syncthreads(); }
    float mx = red[0]; __syncthreads();

    float p0 = m0 ? expf(v0 - mx) : 0.f;
    float p1 = m1 ? expf(v1 - mx) : 0.f;
    red[tid] = p0 + p1; __syncthreads();
    for (int s = 128; s; s >>= 1) { if (tid < s) red[tid] += red[tid + s]; __syncthreads(); }
    float sum = red[0];
    float inv = (sum > 0.f) ? (1.0f / sum) : 0.f;
    g_scores[rowS + k0] = p0 * inv;
    g_scores[rowS + k1] = p1 * inv;
}

// ---------------------------------------------------------------- decoder + per-token NLL
__global__ void decoder_kernel(const float* __restrict__ tin, const float* __restrict__ Wd,
                               const float* __restrict__ bd, const int* __restrict__ labels,
                               float* __restrict__ out, int out_size) {
    __shared__ float sm[HID];
    __shared__ float red[256];
    __shared__ float lg[NCLS];
    int t = blockIdx.x, tid = threadIdx.x;
    for (int i = tid; i < HID; i += 256) sm[i] = tin[(size_t)t * HID + i];
    __syncthreads();
    for (int c = 0; c < NCLS; c++) {
        float p = 0.f;
        for (int k = tid; k < HID; k += 256) p += sm[k] * Wd[(size_t)k * NCLS + c];
        red[tid] = p; __syncthreads();
        for (int s = 128; s; s >>= 1) { if (tid < s) red[tid] += red[tid + s]; __syncthreads(); }
        if (tid == 0) lg[c] = red[0] + bd[c];
        __syncthreads();
    }
    if (out_size >= TOK * NCLS && tid < NCLS) out[(size_t)t * NCLS + tid] = lg[tid];
    if (tid == 0) {
        float mx = -FLT_MAX;
        for (int c = 0; c < NCLS; c++) mx = fmaxf(mx, lg[c]);
        float se = 0.f;
        for (int c = 0; c < NCLS; c++) se += expf(lg[c] - mx);
        float lse = mx + logf(se);
        g_nll[t] = (lse - lg[labels[t]]) * g_maskf[t];
    }
}

// ---------------------------------------------------------------- final deterministic loss reduce
__global__ void loss_kernel(float* __restrict__ out, int out_size) {
    __shared__ float rn[256], rd[256];
    int tid = threadIdx.x;
    float a = 0.f, d = 0.f;
    for (int t = tid; t < TOK; t += 256) { a += g_nll[t]; d += g_maskf[t]; }
    rn[tid] = a; rd[tid] = d; __syncthreads();
    for (int s = 128; s; s >>= 1) {
        if (tid < s) { rn[tid] += rn[tid + s]; rd[tid] += rd[tid + s]; }
        __syncthreads();
    }
    if (tid == 0) {
        float loss = rn[0] / fmaxf(rd[0], 1.0f);
        if (out_size > TOK * NCLS) out[TOK * NCLS] = loss;
        else if (out_size == 1)    out[0] = loss;
    }
}

// ---------------------------------------------------------------- launch
extern "C" void kernel_launch(void* const* d_in, const int* in_sizes, int n_in,
                              void* d_out, int out_size) {
    const float* word_emb = (const float*)d_in[0];
    const float* emb_ln_s = (const float*)d_in[1];
    const float* emb_ln_b = (const float*)d_in[2];
    const float* rel_emb  = (const float*)d_in[3];
    const float* rel_ln_s = (const float*)d_in[4];
    const float* rel_ln_b = (const float*)d_in[5];
    const float* Wq = (const float*)d_in[6];   const float* bq = (const float*)d_in[7];
    const float* Wk = (const float*)d_in[8];   const float* bk = (const float*)d_in[9];
    const float* Wv = (const float*)d_in[10];  const float* bv = (const float*)d_in[11];
    const float* Wo = (const float*)d_in[12];  const float* bo = (const float*)d_in[13];
    const float* ln1_s = (const float*)d_in[14]; const float* ln1_b = (const float*)d_in[15];
    const float* W1 = (const float*)d_in[16];  const float* b1 = (const float*)d_in[17];
    const float* W2 = (const float*)d_in[18];  const float* b2 = (const float*)d_in[19];
    const float* ln2_s = (const float*)d_in[20]; const float* ln2_b = (const float*)d_in[21];
    const float* Wt = (const float*)d_in[22];  const float* bt = (const float*)d_in[23];
    const float* tln_s = (const float*)d_in[24]; const float* tln_b = (const float*)d_in[25];
    const float* Wd = (const float*)d_in[26];  const float* bd = (const float*)d_in[27];
    const int* ids    = (const int*)d_in[28];
    const int* att    = (const int*)d_in[29];
    const int* labels = (const int*)d_in[30];
    float* out = (float*)d_out;
    (void)in_sizes; (void)n_in;

    float *x, *q, *k, *v, *ctx, *tmp, *relln, *posk, *posq, *scores, *c2p, *p2c, *ff;
    cudaGetSymbolAddress((void**)&x, g_x);       cudaGetSymbolAddress((void**)&q, g_q);
    cudaGetSymbolAddress((void**)&k, g_k);       cudaGetSymbolAddress((void**)&v, g_v);
    cudaGetSymbolAddress((void**)&ctx, g_ctx);   cudaGetSymbolAddress((void**)&tmp, g_tmp);
    cudaGetSymbolAddress((void**)&relln, g_relln);
    cudaGetSymbolAddress((void**)&posk, g_posk); cudaGetSymbolAddress((void**)&posq, g_posq);
    cudaGetSymbolAddress((void**)&scores, g_scores);
    cudaGetSymbolAddress((void**)&c2p, g_c2p);   cudaGetSymbolAddress((void**)&p2c, g_p2c);
    cudaGetSymbolAddress((void**)&ff, g_ff);

    embed_kernel<<<TOK, 256>>>(word_emb, emb_ln_s, emb_ln_b, ids, att);
    relidx_kernel<<<(SEQ * SEQ + 255) / 256, 256>>>();
    ln_kernel<<<RSPAN, 256>>>(rel_emb, rel_ln_s, rel_ln_b, relln);

    for (int l = 0; l < NLAYER; l++) {
        const float* wq = Wq + (size_t)l * HID * HID;  const float* bql = bq + (size_t)l * HID;
        const float* wk = Wk + (size_t)l * HID * HID;  const float* bkl = bk + (size_t)l * HID;
        const float* wv = Wv + (size_t)l * HID * HID;  const float* bvl = bv + (size_t)l * HID;
        const float* wo = Wo + (size_t)l * HID * HID;  const float* bol = bo + (size_t)l * HID;
        const float* w1 = W1 + (size_t)l * HID * FFD;  const float* b1l = b1 + (size_t)l * FFD;
        const float* w2 = W2 + (size_t)l * FFD * HID;  const float* b2l = b2 + (size_t)l * HID;

        gemm_nn<0><<<dim3(HID / 64, TOK / 64), 256>>>(x, wq, bql, q, TOK, HID, HID);
        gemm_nn<0><<<dim3(HID / 64, TOK / 64), 256>>>(x, wk, bkl, k, TOK, HID, HID);
        gemm_nn<0><<<dim3(HID / 64, TOK / 64), 256>>>(x, wv, bvl, v, TOK, HID, HID);
        gemm_nn<0><<<dim3(HID / 64, RSPAN / 64), 256>>>(relln, wk, bkl, posk, RSPAN, HID, HID);
        gemm_nn<0><<<dim3(HID / 64, RSPAN / 64), 256>>>(relln, wq, bql, posq, RSPAN, HID, HID);

        // scores[b,h,q,k] = q . k
        bgemm_nt<<<dim3(SEQ / 64, SEQ / 64, ZBATCH), 256>>>(
            q, k, scores, SEQ, SEQ, HDIM, HID, HID, SEQ,
            (long)SEQ * HID, (long)HDIM, (long)SEQ * HID, (long)HDIM, (long)SEQ * SEQ);
        // c2p[b,h,q,r] = q . pos_k[r]
        bgemm_nt<<<dim3(RSPAN / 64, SEQ / 64, ZBATCH), 256>>>(
            q, posk, c2p, SEQ, RSPAN, HDIM, HID, HID, RSPAN,
            (long)SEQ * HID, (long)HDIM, 0L, (long)HDIM, (long)SEQ * RSPAN);
        // p2c[b,h,k,r] = k . pos_q[r]
        bgemm_nt<<<dim3(RSPAN / 64, SEQ / 64, ZBATCH), 256>>>(
            k, posq, p2c, SEQ, RSPAN, HDIM, HID, HID, RSPAN,
            (long)SEQ * HID, (long)HDIM, 0L, (long)HDIM, (long)SEQ * RSPAN);

        softmax_kernel<<<ZBATCH * SEQ, 256>>>();

        // ctx = probs @ V
        bgemm_nn<<<dim3(1, SEQ / 64, ZBATCH), 256>>>(
            scores, v, ctx, SEQ, HDIM, SEQ, SEQ, HID, HID,
            (long)SEQ * SEQ, (long)SEQ * HID, (long)HDIM, (long)SEQ * HID, (long)HDIM);

        gemm_nn<0><<<dim3(HID / 64, TOK / 64), 256>>>(ctx, wo, bol, tmp, TOK, HID, HID);
        add_ln_kernel<<<TOK, 256>>>(x, tmp, ln1_s + (size_t)l * HID, ln1_b + (size_t)l * HID, x);

        gemm_nn<1><<<dim3(FFD / 64, TOK / 64), 256>>>(x, w1, b1l, ff, TOK, FFD, HID);
        gemm_nn<0><<<dim3(HID / 64, TOK / 64), 256>>>(ff, w2, b2l, tmp, TOK, HID, FFD);
        add_ln_kernel<<<TOK, 256>>>(x, tmp, ln2_s + (size_t)l * HID, ln2_b + (size_t)l * HID, x);
    }

    // transform head: LN(gelu(x @ Wt + bt))
    gemm_nn<1><<<dim3(HID / 64, TOK / 64), 256>>>(x, Wt, bt, tmp, TOK, HID, HID);
    ln_kernel<<<TOK, 256>>>(tmp, tln_s, tln_b, q);  // reuse g_q as transform output

    decoder_kernel<<<TOK, 256>>>(q, Wd, bd, labels, out, out_size);
    loss_kernel<<<1, 256>>>(out, out_size);
}

// round 5
// speedup vs baseline: 2.8597x; 2.8597x over previous
#include <cuda_runtime.h>
#include <math.h>
#include <float.h>

// ---------------------------------------------------------------- constants
#define BATCH 2
#define SEQ   512
#define HID   1024
#define NHEAD 16
#define HDIM  64
#define NLAYER 4
#define FFD   4096
#define NCLS  14
#define TOK   (BATCH*SEQ)     // 1024
#define RSPAN 512             // 2*SPAN
#define ZBATCH (BATCH*NHEAD)  // 32

#define BM 128
#define BN 64
#define BKK 16

// ---------------------------------------------------------------- scratch
__device__ float g_x[TOK*HID];
__device__ float g_q[TOK*HID];          // transform-head output
__device__ float g_ctx[TOK*HID];
__device__ float g_tmp[TOK*HID];
__device__ float g_relln[RSPAN*HID];
__device__ float g_qkv[(size_t)TOK*3*HID];
__device__ float g_pos[(size_t)RSPAN*2*HID];
__device__ float g_wcat[(size_t)HID*3*HID];
__device__ float g_bcat[3*HID];
__device__ float g_scores[(size_t)ZBATCH*SEQ*SEQ];
__device__ float g_c2p[(size_t)ZBATCH*SEQ*RSPAN];
__device__ float g_p2c[(size_t)ZBATCH*SEQ*RSPAN];
__device__ float g_ff[(size_t)TOK*FFD];
__device__ int   g_c2pidx[SEQ*SEQ];
__device__ int   g_p2cidx[SEQ*SEQ];
__device__ float g_maskf[TOK];
__device__ float g_nll[TOK];

__device__ __forceinline__ float gelu_exact(float x) {
    return 0.5f * x * (1.0f + erff(x * 0.70710678118654752440f));
}

// ---------------------------------------------------------------- embed + LN + mask
__global__ void embed_kernel(const float* __restrict__ we, const float* __restrict__ sc,
                             const float* __restrict__ bi, const int* __restrict__ ids,
                             const int* __restrict__ att) {
    __shared__ float sm[HID];
    __shared__ float red[256];
    int t = blockIdx.x, tid = threadIdx.x;
    const float* row = we + (size_t)ids[t] * HID;
    float s1 = 0.f;
    for (int i = tid; i < HID; i += 256) { float v = row[i]; sm[i] = v; s1 += v; }
    red[tid] = s1; __syncthreads();
    for (int s = 128; s; s >>= 1) { if (tid < s) red[tid] += red[tid + s]; __syncthreads(); }
    float mu = red[0] * (1.0f / HID); __syncthreads();
    float s2 = 0.f;
    for (int i = tid; i < HID; i += 256) { float d = sm[i] - mu; s2 += d * d; }
    red[tid] = s2; __syncthreads();
    for (int s = 128; s; s >>= 1) { if (tid < s) red[tid] += red[tid + s]; __syncthreads(); }
    float inv = rsqrtf(red[0] * (1.0f / HID) + 1e-7f);
    float mf = (float)att[t];
    if (tid == 0) g_maskf[t] = mf;
    for (int i = tid; i < HID; i += 256)
        g_x[(size_t)t * HID + i] = ((sm[i] - mu) * inv * sc[i] + bi[i]) * mf;
}

// ---------------------------------------------------------------- plain row LN
__global__ void ln_kernel(const float* __restrict__ in, const float* __restrict__ sc,
                          const float* __restrict__ bi, float* __restrict__ out) {
    __shared__ float sm[HID];
    __shared__ float red[256];
    int t = blockIdx.x, tid = threadIdx.x;
    const float* row = in + (size_t)t * HID;
    float s1 = 0.f;
    for (int i = tid; i < HID; i += 256) { float v = row[i]; sm[i] = v; s1 += v; }
    red[tid] = s1; __syncthreads();
    for (int s = 128; s; s >>= 1) { if (tid < s) red[tid] += red[tid + s]; __syncthreads(); }
    float mu = red[0] * (1.0f / HID); __syncthreads();
    float s2 = 0.f;
    for (int i = tid; i < HID; i += 256) { float d = sm[i] - mu; s2 += d * d; }
    red[tid] = s2; __syncthreads();
    for (int s = 128; s; s >>= 1) { if (tid < s) red[tid] += red[tid + s]; __syncthreads(); }
    float inv = rsqrtf(red[0] * (1.0f / HID) + 1e-7f);
    for (int i = tid; i < HID; i += 256)
        out[(size_t)t * HID + i] = (sm[i] - mu) * inv * sc[i] + bi[i];
}

// ---------------------------------------------------------------- residual + LN
__global__ void add_ln_kernel(const float* __restrict__ x, const float* __restrict__ d,
                              const float* __restrict__ sc, const float* __restrict__ bi,
                              float* __restrict__ out) {
    __shared__ float sm[HID];
    __shared__ float red[256];
    int t = blockIdx.x, tid = threadIdx.x;
    float s1 = 0.f;
    for (int i = tid; i < HID; i += 256) {
        float v = x[(size_t)t * HID + i] + d[(size_t)t * HID + i];
        sm[i] = v; s1 += v;
    }
    red[tid] = s1; __syncthreads();
    for (int s = 128; s; s >>= 1) { if (tid < s) red[tid] += red[tid + s]; __syncthreads(); }
    float mu = red[0] * (1.0f / HID); __syncthreads();
    float s2 = 0.f;
    for (int i = tid; i < HID; i += 256) { float dv = sm[i] - mu; s2 += dv * dv; }
    red[tid] = s2; __syncthreads();
    for (int s = 128; s; s >>= 1) { if (tid < s) red[tid] += red[tid + s]; __syncthreads(); }
    float inv = rsqrtf(red[0] * (1.0f / HID) + 1e-7f);
    for (int i = tid; i < HID; i += 256)
        out[(size_t)t * HID + i] = (sm[i] - mu) * inv * sc[i] + bi[i];
}

// ---------------------------------------------------------------- relative-position buckets
__global__ void relidx_kernel() {
    int idx = blockIdx.x * blockDim.x + threadIdx.x;
    if (idx >= SEQ * SEQ) return;
    int i = idx >> 9, j = idx & 511;
    int rel = i - j;
    const int mid = 128;
    int apos = (rel < mid && rel > -mid) ? (mid - 1) : (rel < 0 ? -rel : rel);
    int bucket;
    if (apos <= mid) {
        bucket = rel;
    } else {
        const float LOGC = logf(511.0f / 128.0f);
        float lp = ceilf(logf((float)apos / 128.0f) / LOGC * 127.0f) + 128.0f;
        float sg = (rel > 0) ? 1.0f : ((rel < 0) ? -1.0f : 0.0f);
        bucket = (int)(lp * sg);
    }
    int c = bucket + 256;  c = c < 0 ? 0 : (c > 511 ? 511 : c);
    int p = -bucket + 256; p = p < 0 ? 0 : (p > 511 ? 511 : p);
    g_c2pidx[idx] = c;
    g_p2cidx[idx] = p;
}

// ---------------------------------------------------------------- weight concat (QKV fusion)
__global__ void concat_w_kernel(const float* __restrict__ Wq, const float* __restrict__ Wk,
                                const float* __restrict__ Wv,
                                const float* __restrict__ bq, const float* __restrict__ bk,
                                const float* __restrict__ bv) {
    int idx = blockIdx.x * 256 + threadIdx.x;   // over HID*HID/4 = 262144 float4s
    const float4* q4 = (const float4*)Wq;
    const float4* k4 = (const float4*)Wk;
    const float4* v4 = (const float4*)Wv;
    float4* w = (float4*)g_wcat;
    int k = idx >> 8;          // row (HID/4 = 256 f4 per source row)
    int c = idx & 255;
    w[(size_t)k * 768 + c]       = q4[idx];
    w[(size_t)k * 768 + 256 + c] = k4[idx];
    w[(size_t)k * 768 + 512 + c] = v4[idx];
    if (idx < 256) {
        float4* b = (float4*)g_bcat;
        b[idx]       = ((const float4*)bq)[idx];
        b[256 + idx] = ((const float4*)bk)[idx];
        b[512 + idx] = ((const float4*)bv)[idx];
    }
}

// ---------------------------------------------------------------- universal tiled GEMM
// C[M,N] = A @ B(^T) (+bias) (+gelu).  128x64 block tile, BK=16, 256 thr, 8x4 micro.
// Batched via z = blockIdx.z: ptr += (z>>4)*·B + (z&15)*·H strides.
template<int TRANS_B, int HAS_BIAS, int ACT>
__global__ void __launch_bounds__(256, 2) gemm_tile(
    const float* __restrict__ A, const float* __restrict__ B,
    const float* __restrict__ bias, float* __restrict__ C,
    int K, int lda, int ldb, int ldc,
    long aB, long aH, long bB, long bH, long cB, long cH)
{
    __shared__ float As[2][BKK * BM];
    __shared__ float Bs[2][BKK * BN];
    int tid = threadIdx.x;
    int z = blockIdx.z, bb = z >> 4, hh = z & 15;
    const float* Az = A + (size_t)bb * aB + (size_t)hh * aH;
    const float* Bz = B + (size_t)bb * bB + (size_t)hh * bH;
    float*       Cz = C + (size_t)bb * cB + (size_t)hh * cH;
    int bm = blockIdx.y * BM, bn = blockIdx.x * BN;
    int tx = tid & 15, ty = tid >> 4;

    float4 aReg[2];
    float4 bReg;
    // A: 512 float4s, 2 per thread. id -> row = id>>2, col4 = id&3 (coalesced ldg)
    // B-NN: 256 f4: row = tid>>4, col4 = tid&15 (coalesced, direct f4 sts)
    // B-NT: 256 f4: nrow = tid>>2, kcol4 = tid&3 (coalesced, transposed sts)

    auto ldg = [&](int k0) {
#pragma unroll
        for (int i = 0; i < 2; i++) {
            int id = tid + i * 256;
            aReg[i] = *(const float4*)(Az + (size_t)(bm + (id >> 2)) * lda + k0 + (id & 3) * 4);
        }
        if (TRANS_B)
            bReg = *(const float4*)(Bz + (size_t)(bn + (tid >> 2)) * ldb + k0 + (tid & 3) * 4);
        else
            bReg = *(const float4*)(Bz + (size_t)(k0 + (tid >> 4)) * ldb + bn + (tid & 15) * 4);
    };
    auto sts = [&](int buf) {
#pragma unroll
        for (int i = 0; i < 2; i++) {
            int id = tid + i * 256;
            int ar = id >> 2, ac = (id & 3) * 4;
            As[buf][(ac + 0) * BM + ar] = aReg[i].x;
            As[buf][(ac + 1) * BM + ar] = aReg[i].y;
            As[buf][(ac + 2) * BM + ar] = aReg[i].z;
            As[buf][(ac + 3) * BM + ar] = aReg[i].w;
        }
        if (TRANS_B) {
            int nr = tid >> 2, kc = (tid & 3) * 4;
            Bs[buf][(kc + 0) * BN + nr] = bReg.x;
            Bs[buf][(kc + 1) * BN + nr] = bReg.y;
            Bs[buf][(kc + 2) * BN + nr] = bReg.z;
            Bs[buf][(kc + 3) * BN + nr] = bReg.w;
        } else {
            *(float4*)&Bs[buf][(tid >> 4) * BN + (tid & 15) * 4] = bReg;
        }
    };

    float acc[8][4] = {};
    ldg(0);
    sts(0);
    __syncthreads();
    int nk = K / BKK;
    for (int kt = 0; kt < nk; kt++) {
        int cur = kt & 1;
        if (kt + 1 < nk) ldg((kt + 1) * BKK);
#pragma unroll
        for (int kk = 0; kk < BKK; kk++) {
            float4 a0 = *(const float4*)&As[cur][kk * BM + ty * 8];
            float4 a1 = *(const float4*)&As[cur][kk * BM + ty * 8 + 4];
            float4 b0 = *(const float4*)&Bs[cur][kk * BN + tx * 4];
            float av[8] = {a0.x, a0.y, a0.z, a0.w, a1.x, a1.y, a1.z, a1.w};
            float bv[4] = {b0.x, b0.y, b0.z, b0.w};
#pragma unroll
            for (int i = 0; i < 8; i++)
#pragma unroll
                for (int j = 0; j < 4; j++) acc[i][j] += av[i] * bv[j];
        }
        if (kt + 1 < nk) { sts(cur ^ 1); __syncthreads(); }
    }

    float4 b4 = make_float4(0.f, 0.f, 0.f, 0.f);
    if (HAS_BIAS) b4 = *(const float4*)(bias + bn + tx * 4);
#pragma unroll
    for (int i = 0; i < 8; i++) {
        float4 r;
        r.x = acc[i][0] + b4.x;
        r.y = acc[i][1] + b4.y;
        r.z = acc[i][2] + b4.z;
        r.w = acc[i][3] + b4.w;
        if (ACT) {
            r.x = gelu_exact(r.x); r.y = gelu_exact(r.y);
            r.z = gelu_exact(r.z); r.w = gelu_exact(r.w);
        }
        *(float4*)(Cz + (size_t)(bm + ty * 8 + i) * ldc + bn + tx * 4) = r;
    }
}

// ---------------------------------------------------------------- combine biases + scale + mask + XSoftmax
__global__ void softmax_kernel() {
    __shared__ float red[256];
    int zq = blockIdx.x;
    int z = zq >> 9, q = zq & 511;
    int bb = z / NHEAD;
    int tid = threadIdx.x;
    const float SCALE = sqrtf(192.0f);  // sqrt(D*3)
    float mq = g_maskf[bb * SEQ + q];
    size_t rowS = ((size_t)z * SEQ + q) * SEQ;
    size_t rowC = ((size_t)z * SEQ + q) * RSPAN;

    int k0 = tid, k1 = tid + 256;
    float s0 = g_scores[rowS + k0]
             + g_c2p[rowC + g_c2pidx[q * SEQ + k0]]
             + g_p2c[((size_t)z * SEQ + k0) * RSPAN + g_p2cidx[k0 * SEQ + q]];
    float s1 = g_scores[rowS + k1]
             + g_c2p[rowC + g_c2pidx[q * SEQ + k1]]
             + g_p2c[((size_t)z * SEQ + k1) * RSPAN + g_p2cidx[k1 * SEQ + q]];
    s0 /= SCALE; s1 /= SCALE;
    bool m0 = (mq * g_maskf[bb * SEQ + k0]) > 0.f;
    bool m1 = (mq * g_maskf[bb * SEQ + k1]) > 0.f;
    float v0 = m0 ? s0 : -FLT_MAX;
    float v1 = m1 ? s1 : -FLT_MAX;

    red[tid] = fmaxf(v0, v1); __syncthreads();
    for (int s = 128; s; s >>= 1) { if (tid < s) red[tid] = fmaxf(red[tid], red[tid + s]); __syncthreads(); }
    float mx = red[0]; __syncthreads();

    float p0 = m0 ? expf(v0 - mx) : 0.f;
    float p1 = m1 ? expf(v1 - mx) : 0.f;
    red[tid] = p0 + p1; __syncthreads();
    for (int s = 128; s; s >>= 1) { if (tid < s) red[tid] += red[tid + s]; __syncthreads(); }
    float sum = red[0];
    float inv = (sum > 0.f) ? (1.0f / sum) : 0.f;
    g_scores[rowS + k0] = p0 * inv;
    g_scores[rowS + k1] = p1 * inv;
}

// ---------------------------------------------------------------- decoder + per-token NLL
__global__ void decoder_kernel(const float* __restrict__ tin, const float* __restrict__ Wd,
                               const float* __restrict__ bd, const int* __restrict__ labels,
                               float* __restrict__ out, int out_size) {
    __shared__ float sm[HID];
    __shared__ float red[256];
    __shared__ float lg[NCLS];
    int t = blockIdx.x, tid = threadIdx.x;
    for (int i = tid; i < HID; i += 256) sm[i] = tin[(size_t)t * HID + i];
    __syncthreads();
    for (int c = 0; c < NCLS; c++) {
        float p = 0.f;
        for (int k = tid; k < HID; k += 256) p += sm[k] * Wd[(size_t)k * NCLS + c];
        red[tid] = p; __syncthreads();
        for (int s = 128; s; s >>= 1) { if (tid < s) red[tid] += red[tid + s]; __syncthreads(); }
        if (tid == 0) lg[c] = red[0] + bd[c];
        __syncthreads();
    }
    if (out_size >= TOK * NCLS && tid < NCLS) out[(size_t)t * NCLS + tid] = lg[tid];
    if (tid == 0) {
        float mx = -FLT_MAX;
        for (int c = 0; c < NCLS; c++) mx = fmaxf(mx, lg[c]);
        float se = 0.f;
        for (int c = 0; c < NCLS; c++) se += expf(lg[c] - mx);
        float lse = mx + logf(se);
        g_nll[t] = (lse - lg[labels[t]]) * g_maskf[t];
    }
}

// ---------------------------------------------------------------- final deterministic loss reduce
__global__ void loss_kernel(float* __restrict__ out, int out_size) {
    __shared__ float rn[256], rd[256];
    int tid = threadIdx.x;
    float a = 0.f, d = 0.f;
    for (int t = tid; t < TOK; t += 256) { a += g_nll[t]; d += g_maskf[t]; }
    rn[tid] = a; rd[tid] = d; __syncthreads();
    for (int s = 128; s; s >>= 1) {
        if (tid < s) { rn[tid] += rn[tid + s]; rd[tid] += rd[tid + s]; }
        __syncthreads();
    }
    if (tid == 0) {
        float loss = rn[0] / fmaxf(rd[0], 1.0f);
        if (out_size > TOK * NCLS) out[TOK * NCLS] = loss;
        else if (out_size == 1)    out[0] = loss;
    }
}

// ---------------------------------------------------------------- launch
extern "C" void kernel_launch(void* const* d_in, const int* in_sizes, int n_in,
                              void* d_out, int out_size) {
    const float* word_emb = (const float*)d_in[0];
    const float* emb_ln_s = (const float*)d_in[1];
    const float* emb_ln_b = (const float*)d_in[2];
    const float* rel_emb  = (const float*)d_in[3];
    const float* rel_ln_s = (const float*)d_in[4];
    const float* rel_ln_b = (const float*)d_in[5];
    const float* Wq = (const float*)d_in[6];   const float* bq = (const float*)d_in[7];
    const float* Wk = (const float*)d_in[8];   const float* bk = (const float*)d_in[9];
    const float* Wv = (const float*)d_in[10];  const float* bv = (const float*)d_in[11];
    const float* Wo = (const float*)d_in[12];  const float* bo = (const float*)d_in[13];
    const float* ln1_s = (const float*)d_in[14]; const float* ln1_b = (const float*)d_in[15];
    const float* W1 = (const float*)d_in[16];  const float* b1 = (const float*)d_in[17];
    const float* W2 = (const float*)d_in[18];  const float* b2 = (const float*)d_in[19];
    const float* ln2_s = (const float*)d_in[20]; const float* ln2_b = (const float*)d_in[21];
    const float* Wt = (const float*)d_in[22];  const float* bt = (const float*)d_in[23];
    const float* tln_s = (const float*)d_in[24]; const float* tln_b = (const float*)d_in[25];
    const float* Wd = (const float*)d_in[26];  const float* bd = (const float*)d_in[27];
    const int* ids    = (const int*)d_in[28];
    const int* att    = (const int*)d_in[29];
    const int* labels = (const int*)d_in[30];
    float* out = (float*)d_out;
    (void)in_sizes; (void)n_in;

    float *x, *qbuf, *ctx, *tmp, *relln, *qkv, *pos, *wcat, *bcat, *scores, *c2p, *p2c, *ff;
    cudaGetSymbolAddress((void**)&x, g_x);       cudaGetSymbolAddress((void**)&qbuf, g_q);
    cudaGetSymbolAddress((void**)&ctx, g_ctx);   cudaGetSymbolAddress((void**)&tmp, g_tmp);
    cudaGetSymbolAddress((void**)&relln, g_relln);
    cudaGetSymbolAddress((void**)&qkv, g_qkv);   cudaGetSymbolAddress((void**)&pos, g_pos);
    cudaGetSymbolAddress((void**)&wcat, g_wcat); cudaGetSymbolAddress((void**)&bcat, g_bcat);
    cudaGetSymbolAddress((void**)&scores, g_scores);
    cudaGetSymbolAddress((void**)&c2p, g_c2p);   cudaGetSymbolAddress((void**)&p2c, g_p2c);
    cudaGetSymbolAddress((void**)&ff, g_ff);

    embed_kernel<<<TOK, 256>>>(word_emb, emb_ln_s, emb_ln_b, ids, att);
    relidx_kernel<<<(SEQ * SEQ + 255) / 256, 256>>>();
    ln_kernel<<<RSPAN, 256>>>(rel_emb, rel_ln_s, rel_ln_b, relln);

    const long SH3 = (long)SEQ * 3 * HID;   // qkv batch-row stride
    const long SS  = (long)SEQ * SEQ;
    const long SR  = (long)SEQ * RSPAN;

    for (int l = 0; l < NLAYER; l++) {
        const float* wo = Wo + (size_t)l * HID * HID;  const float* bol = bo + (size_t)l * HID;
        const float* w1 = W1 + (size_t)l * HID * FFD;  const float* b1l = b1 + (size_t)l * FFD;
        const float* w2 = W2 + (size_t)l * FFD * HID;  const float* b2l = b2 + (size_t)l * HID;

        concat_w_kernel<<<HID * HID / 4 / 256, 256>>>(
            Wq + (size_t)l * HID * HID, Wk + (size_t)l * HID * HID, Wv + (size_t)l * HID * HID,
            bq + (size_t)l * HID, bk + (size_t)l * HID, bv + (size_t)l * HID);

        // fused QKV: [1024,1024] @ [1024,3072]
        gemm_tile<0, 1, 0><<<dim3(3 * HID / BN, TOK / BM, 1), 256>>>(
            x, wcat, bcat, qkv, HID, HID, 3 * HID, 3 * HID, 0, 0, 0, 0, 0, 0);
        // fused pos_q|pos_k: [512,1024] @ [1024,2048]
        gemm_tile<0, 1, 0><<<dim3(2 * HID / BN, RSPAN / BM, 1), 256>>>(
            relln, wcat, bcat, pos, HID, HID, 3 * HID, 2 * HID, 0, 0, 0, 0, 0, 0);

        // scores[b,h,q,k] = q.k   (NT, K=64)
        gemm_tile<1, 0, 0><<<dim3(SEQ / BN, SEQ / BM, ZBATCH), 256>>>(
            qkv, qkv + HID, nullptr, scores, HDIM, 3 * HID, 3 * HID, SEQ,
            SH3, (long)HDIM, SH3, (long)HDIM, (long)NHEAD * SS, SS);
        // c2p[b,h,q,r] = q.posk[r]
        gemm_tile<1, 0, 0><<<dim3(RSPAN / BN, SEQ / BM, ZBATCH), 256>>>(
            qkv, pos + HID, nullptr, c2p, HDIM, 3 * HID, 2 * HID, RSPAN,
            SH3, (long)HDIM, 0L, (long)HDIM, (long)NHEAD * SR, SR);
        // p2c[b,h,k,r] = k.posq[r]
        gemm_tile<1, 0, 0><<<dim3(RSPAN / BN, SEQ / BM, ZBATCH), 256>>>(
            qkv + HID, pos, nullptr, p2c, HDIM, 3 * HID, 2 * HID, RSPAN,
            SH3, (long)HDIM, 0L, (long)HDIM, (long)NHEAD * SR, SR);

        softmax_kernel<<<ZBATCH * SEQ, 256>>>();

        // ctx = probs @ V  (NN, N=64, K=512)
        gemm_tile<0, 0, 0><<<dim3(1, SEQ / BM, ZBATCH), 256>>>(
            scores, qkv + 2 * HID, nullptr, ctx, SEQ, SEQ, 3 * HID, HID,
            (long)NHEAD * SS, SS, SH3, (long)HDIM, (long)SEQ * HID, (long)HDIM);

        gemm_tile<0, 1, 0><<<dim3(HID / BN, TOK / BM, 1), 256>>>(
            ctx, wo, bol, tmp, HID, HID, HID, HID, 0, 0, 0, 0, 0, 0);
        add_ln_kernel<<<TOK, 256>>>(x, tmp, ln1_s + (size_t)l * HID, ln1_b + (size_t)l * HID, x);

        gemm_tile<0, 1, 1><<<dim3(FFD / BN, TOK / BM, 1), 256>>>(
            x, w1, b1l, ff, HID, HID, FFD, FFD, 0, 0, 0, 0, 0, 0);
        gemm_tile<0, 1, 0><<<dim3(HID / BN, TOK / BM, 1), 256>>>(
            ff, w2, b2l, tmp, FFD, FFD, HID, HID, 0, 0, 0, 0, 0, 0);
        add_ln_kernel<<<TOK, 256>>>(x, tmp, ln2_s + (size_t)l * HID, ln2_b + (size_t)l * HID, x);
    }

    // transform head: LN(gelu(x @ Wt + bt))
    gemm_tile<0, 1, 1><<<dim3(HID / BN, TOK / BM, 1), 256>>>(
        x, Wt, bt, tmp, HID, HID, HID, HID, 0, 0, 0, 0, 0, 0);
    ln_kernel<<<TOK, 256>>>(tmp, tln_s, tln_b, qbuf);

    decoder_kernel<<<TOK, 256>>>(qbuf, Wd, bd, labels, out, out_size);
    loss_kernel<<<1, 256>>>(out, out_size);
}

// round 8
// speedup vs baseline: 5.3962x; 1.8870x over previous
#include <cuda_runtime.h>
#include <math.h>
#include <float.h>
#include <stdint.h>

// ---------------------------------------------------------------- constants
#define BATCH 2
#define SEQ   512
#define HID   1024
#define NHEAD 16
#define HDIM  64
#define NLAYER 4
#define FFD   4096
#define NCLS  14
#define TOK   (BATCH*SEQ)     // 1024
#define RSPAN 512             // 2*SPAN
#define ZBATCH (BATCH*NHEAD)  // 32

#define BM 128
#define BN 64
#define LDS_ 36               // BK(32) + 4 pad
#define SMEM_BYTES ((2*BM*LDS_ + 2*BN*LDS_) * 4)   // 55296

// ---------------------------------------------------------------- scratch
__device__ float g_x[TOK*HID];
__device__ float g_q[TOK*HID];          // transform-head output
__device__ float g_ctx[TOK*HID];
__device__ float g_tmp[TOK*HID];
__device__ float g_relln[RSPAN*HID];
__device__ float g_qkv[(size_t)TOK*3*HID];
__device__ float g_pos[(size_t)RSPAN*2*HID];
__device__ float g_wcatT[(size_t)3*HID*HID];   // [3072][1024]  (n-major)
__device__ float g_bcat[3*HID];
__device__ float g_woT[(size_t)HID*HID];
__device__ float g_w1T[(size_t)FFD*HID];
__device__ float g_w2T[(size_t)HID*FFD];
__device__ float g_wtT[(size_t)HID*HID];
__device__ float g_vt[(size_t)ZBATCH*HDIM*SEQ];  // [z][d][s]
__device__ float g_scores[(size_t)ZBATCH*SEQ*SEQ];
__device__ float g_c2p[(size_t)ZBATCH*SEQ*RSPAN];
__device__ float g_p2c[(size_t)ZBATCH*SEQ*RSPAN];
__device__ float g_ff[(size_t)TOK*FFD];
__device__ int   g_c2pidx[SEQ*SEQ];
__device__ int   g_p2cidx[SEQ*SEQ];
__device__ float g_maskf[TOK];
__device__ float g_nll[TOK];

__device__ __forceinline__ float gelu_exact(float x) {
    return 0.5f * x * (1.0f + erff(x * 0.70710678118654752440f));
}
__device__ __forceinline__ float tf32r(float x) {
    uint32_t u; asm("cvt.rna.tf32.f32 %0, %1;" : "=r"(u) : "f"(x));
    return __uint_as_float(u);
}
__device__ __forceinline__ void ldsm4(uint32_t* r, uint32_t addr) {
    asm volatile("ldmatrix.sync.aligned.m8n8.x4.shared.b16 {%0,%1,%2,%3}, [%4];"
                 : "=r"(r[0]), "=r"(r[1]), "=r"(r[2]), "=r"(r[3]) : "r"(addr));
}
__device__ __forceinline__ void mma_tf32(float* c, const uint32_t* a, uint32_t b0, uint32_t b1) {
    asm volatile(
        "mma.sync.aligned.m16n8k8.row.col.f32.tf32.tf32.f32 "
        "{%0,%1,%2,%3}, {%4,%5,%6,%7}, {%8,%9}, {%0,%1,%2,%3};"
        : "+f"(c[0]), "+f"(c[1]), "+f"(c[2]), "+f"(c[3])
        : "r"(a[0]), "r"(a[1]), "r"(a[2]), "r"(a[3]), "r"(b0), "r"(b1));
}

// ---------------------------------------------------------------- embed + LN + mask
__global__ void embed_kernel(const float* __restrict__ we, const float* __restrict__ sc,
                             const float* __restrict__ bi, const int* __restrict__ ids,
                             const int* __restrict__ att) {
    __shared__ float sm[HID];
    __shared__ float red[256];
    int t = blockIdx.x, tid = threadIdx.x;
    const float* row = we + (size_t)ids[t] * HID;
    float s1 = 0.f;
    for (int i = tid; i < HID; i += 256) { float v = row[i]; sm[i] = v; s1 += v; }
    red[tid] = s1; __syncthreads();
    for (int s = 128; s; s >>= 1) { if (tid < s) red[tid] += red[tid + s]; __syncthreads(); }
    float mu = red[0] * (1.0f / HID); __syncthreads();
    float s2 = 0.f;
    for (int i = tid; i < HID; i += 256) { float d = sm[i] - mu; s2 += d * d; }
    red[tid] = s2; __syncthreads();
    for (int s = 128; s; s >>= 1) { if (tid < s) red[tid] += red[tid + s]; __syncthreads(); }
    float inv = rsqrtf(red[0] * (1.0f / HID) + 1e-7f);
    float mf = (float)att[t];
    if (tid == 0) g_maskf[t] = mf;
    for (int i = tid; i < HID; i += 256)
        g_x[(size_t)t * HID + i] = ((sm[i] - mu) * inv * sc[i] + bi[i]) * mf;
}

// ---------------------------------------------------------------- plain row LN
__global__ void ln_kernel(const float* __restrict__ in, const float* __restrict__ sc,
                          const float* __restrict__ bi, float* __restrict__ out) {
    __shared__ float sm[HID];
    __shared__ float red[256];
    int t = blockIdx.x, tid = threadIdx.x;
    const float* row = in + (size_t)t * HID;
    float s1 = 0.f;
    for (int i = tid; i < HID; i += 256) { float v = row[i]; sm[i] = v; s1 += v; }
    red[tid] = s1; __syncthreads();
    for (int s = 128; s; s >>= 1) { if (tid < s) red[tid] += red[tid + s]; __syncthreads(); }
    float mu = red[0] * (1.0f / HID); __syncthreads();
    float s2 = 0.f;
    for (int i = tid; i < HID; i += 256) { float d = sm[i] - mu; s2 += d * d; }
    red[tid] = s2; __syncthreads();
    for (int s = 128; s; s >>= 1) { if (tid < s) red[tid] += red[tid + s]; __syncthreads(); }
    float inv = rsqrtf(red[0] * (1.0f / HID) + 1e-7f);
    for (int i = tid; i < HID; i += 256)
        out[(size_t)t * HID + i] = (sm[i] - mu) * inv * sc[i] + bi[i];
}

// ---------------------------------------------------------------- residual + LN
__global__ void add_ln_kernel(const float* __restrict__ x, const float* __restrict__ d,
                              const float* __restrict__ sc, const float* __restrict__ bi,
                              float* __restrict__ out) {
    __shared__ float sm[HID];
    __shared__ float red[256];
    int t = blockIdx.x, tid = threadIdx.x;
    float s1 = 0.f;
    for (int i = tid; i < HID; i += 256) {
        float v = x[(size_t)t * HID + i] + d[(size_t)t * HID + i];
        sm[i] = v; s1 += v;
    }
    red[tid] = s1; __syncthreads();
    for (int s = 128; s; s >>= 1) { if (tid < s) red[tid] += red[tid + s]; __syncthreads(); }
    float mu = red[0] * (1.0f / HID); __syncthreads();
    float s2 = 0.f;
    for (int i = tid; i < HID; i += 256) { float dv = sm[i] - mu; s2 += dv * dv; }
    red[tid] = s2; __syncthreads();
    for (int s = 128; s; s >>= 1) { if (tid < s) red[tid] += red[tid + s]; __syncthreads(); }
    float inv = rsqrtf(red[0] * (1.0f / HID) + 1e-7f);
    for (int i = tid; i < HID; i += 256)
        out[(size_t)t * HID + i] = (sm[i] - mu) * inv * sc[i] + bi[i];
}

// ---------------------------------------------------------------- relative-position buckets
__global__ void relidx_kernel() {
    int idx = blockIdx.x * blockDim.x + threadIdx.x;
    if (idx >= SEQ * SEQ) return;
    int i = idx >> 9, j = idx & 511;
    int rel = i - j;
    const int mid = 128;
    int apos = (rel < mid && rel > -mid) ? (mid - 1) : (rel < 0 ? -rel : rel);
    int bucket;
    if (apos <= mid) {
        bucket = rel;
    } else {
        const float LOGC = logf(511.0f / 128.0f);
        float lp = ceilf(logf((float)apos / 128.0f) / LOGC * 127.0f) + 128.0f;
        float sg = (rel > 0) ? 1.0f : ((rel < 0) ? -1.0f : 0.0f);
        bucket = (int)(lp * sg);
    }
    int c = bucket + 256;  c = c < 0 ? 0 : (c > 511 ? 511 : c);
    int p = -bucket + 256; p = p < 0 ? 0 : (p > 511 ? 511 : p);
    g_c2pidx[idx] = c;
    g_p2cidx[idx] = p;
}

// ---------------------------------------------------------------- generic transpose  dst[C][R] = src[R][C]^T
__global__ void transpose_kernel(float* __restrict__ dst, const float* __restrict__ src,
                                 int R, int C) {
    __shared__ float t[32][33];
    int bx = blockIdx.x * 32, by = blockIdx.y * 32;
    int x = threadIdx.x, y = threadIdx.y;
#pragma unroll
    for (int i = 0; i < 32; i += 8)
        t[y + i][x] = src[(size_t)(by + y + i) * C + bx + x];
    __syncthreads();
#pragma unroll
    for (int i = 0; i < 32; i += 8)
        dst[(size_t)(bx + y + i) * R + by + x] = t[x][y + i];
}

// ---------------------------------------------------------------- V transpose: vt[z][d][s]
__global__ void vtrans_kernel(const float* __restrict__ qkv, float* __restrict__ vt) {
    __shared__ float t[32][33];
    int z = blockIdx.z, bb = z >> 4, h = z & 15;
    int s0 = blockIdx.x * 32, d0 = blockIdx.y * 32;
    const float* src = qkv + (size_t)bb * SEQ * 3 * HID + 2 * HID + h * 64;
    int x = threadIdx.x, y = threadIdx.y;
#pragma unroll
    for (int i = 0; i < 32; i += 8)
        t[y + i][x] = src[(size_t)(s0 + y + i) * 3 * HID + d0 + x];
    __syncthreads();
    float* dst = vt + (size_t)z * HDIM * SEQ;
#pragma unroll
    for (int i = 0; i < 32; i += 8)
        dst[(size_t)(d0 + y + i) * SEQ + s0 + x] = t[x][y + i];
}

// ---------------------------------------------------------------- bias concat
__global__ void bcat_kernel(const float* __restrict__ bq, const float* __restrict__ bk,
                            const float* __restrict__ bv) {
    int idx = blockIdx.x * 256 + threadIdx.x;
    if (idx >= 3 * HID) return;
    int sel = idx >> 10, c = idx & 1023;
    g_bcat[idx] = (sel == 0) ? bq[c] : (sel == 1 ? bk[c] : bv[c]);
}

// ---------------------------------------------------------------- TF32 tensor-core GEMM (NT)
// C[M,N] = A[M,K] @ B[N,K]^T (+bias) (+gelu).  128x64 tile, BK=32, 256 thr.
// Batched via z = blockIdx.z: bb = z>>4, hh = z&15.
template<int HAS_BIAS, int ACT>
__global__ void __launch_bounds__(256, 2) gemm_tc(
    const float* __restrict__ A, const float* __restrict__ B,
    const float* __restrict__ bias, float* __restrict__ C,
    int K, int lda, int ldb, int ldc,
    long aB, long aH, long bB, long bH, long cB, long cH)
{
    extern __shared__ float smem[];
    float* As = smem;                      // [2][BM*LDS_]
    float* Bs = smem + 2 * BM * LDS_;      // [2][BN*LDS_]
    const int tid = threadIdx.x;
    const int lane = tid & 31, wid = tid >> 5;
    const int wm = (wid & 3) * 32, wn = (wid >> 2) * 32;
    const int z = blockIdx.z, bb = z >> 4, hh = z & 15;
    const float* Az = A + (size_t)bb * aB + (size_t)hh * aH;
    const float* Bz = B + (size_t)bb * bB + (size_t)hh * bH;
    float*       Cz = C + (size_t)bb * cB + (size_t)hh * cH;
    const int bm = blockIdx.y * BM, bn = blockIdx.x * BN;

    const uint32_t sA = (uint32_t)__cvta_generic_to_shared(As);
    const uint32_t sB = (uint32_t)__cvta_generic_to_shared(Bs);

    // ldmatrix lane geometry (b16-pair trick for tf32)
    const int a_row = (lane & 7) + ((lane >> 3) & 1) * 8;
    const int a_kad = (lane >> 4) * 4;
    const int b_row = (lane & 7) + (lane >> 4) * 8;
    const int b_kad = ((lane >> 3) & 1) * 4;

    float4 aR[4], bR[2];
    auto ldg = [&](int k0) {
#pragma unroll
        for (int i = 0; i < 4; i++) {
            int id = tid + i * 256;
            aR[i] = *(const float4*)(Az + (size_t)(bm + (id >> 3)) * lda + k0 + (id & 7) * 4);
        }
#pragma unroll
        for (int i = 0; i < 2; i++) {
            int id = tid + i * 256;
            bR[i] = *(const float4*)(Bz + (size_t)(bn + (id >> 3)) * ldb + k0 + (id & 7) * 4);
        }
    };
    auto sts = [&](int buf) {
        float* Ab = As + buf * BM * LDS_;
        float* Bb = Bs + buf * BN * LDS_;
#pragma unroll
        for (int i = 0; i < 4; i++) {
            int id = tid + i * 256;
            float4 v = aR[i];
            float4 w = make_float4(tf32r(v.x), tf32r(v.y), tf32r(v.z), tf32r(v.w));
            *(float4*)(Ab + (id >> 3) * LDS_ + (id & 7) * 4) = w;
        }
#pragma unroll
        for (int i = 0; i < 2; i++) {
            int id = tid + i * 256;
            float4 v = bR[i];
            float4 w = make_float4(tf32r(v.x), tf32r(v.y), tf32r(v.z), tf32r(v.w));
            *(float4*)(Bb + (id >> 3) * LDS_ + (id & 7) * 4) = w;
        }
    };

    float acc[2][4][4];
#pragma unroll
    for (int i = 0; i < 2; i++)
#pragma unroll
        for (int j = 0; j < 4; j++)
#pragma unroll
            for (int c = 0; c < 4; c++) acc[i][j][c] = 0.f;

    ldg(0);
    sts(0);
    __syncthreads();
    const int nk = K >> 5;
    for (int kt = 0; kt < nk; kt++) {
        int cur = kt & 1;
        if (kt + 1 < nk) ldg((kt + 1) * 32);
        uint32_t baseA = sA + (uint32_t)(cur * BM * LDS_) * 4u;
        uint32_t baseB = sB + (uint32_t)(cur * BN * LDS_) * 4u;
#pragma unroll
        for (int kk = 0; kk < 32; kk += 8) {
            uint32_t a[2][4], b[2][4];
#pragma unroll
            for (int i = 0; i < 2; i++)
                ldsm4(a[i], baseA + (uint32_t)((wm + 16 * i + a_row) * LDS_ + kk + a_kad) * 4u);
#pragma unroll
            for (int j2 = 0; j2 < 2; j2++)
                ldsm4(b[j2], baseB + (uint32_t)((wn + 16 * j2 + b_row) * LDS_ + kk + b_kad) * 4u);
#pragma unroll
            for (int i = 0; i < 2; i++)
#pragma unroll
                for (int j = 0; j < 4; j++)
                    mma_tf32(acc[i][j], a[i], b[j >> 1][(j & 1) * 2], b[j >> 1][(j & 1) * 2 + 1]);
        }
        if (kt + 1 < nk) {
            __syncthreads();
            sts(cur ^ 1);
            __syncthreads();
        }
    }

    const int r = lane >> 2, cp = (lane & 3) * 2;
#pragma unroll
    for (int i = 0; i < 2; i++) {
#pragma unroll
        for (int j = 0; j < 4; j++) {
            int row0 = bm + wm + 16 * i + r;
            int col  = bn + wn + 8 * j + cp;
            float2 bb2 = make_float2(0.f, 0.f);
            if (HAS_BIAS) bb2 = *(const float2*)(bias + col);
            float2 v0 = make_float2(acc[i][j][0] + bb2.x, acc[i][j][1] + bb2.y);
            float2 v1 = make_float2(acc[i][j][2] + bb2.x, acc[i][j][3] + bb2.y);
            if (ACT) {
                v0.x = gelu_exact(v0.x); v0.y = gelu_exact(v0.y);
                v1.x = gelu_exact(v1.x); v1.y = gelu_exact(v1.y);
            }
            *(float2*)(Cz + (size_t)row0 * ldc + col) = v0;
            *(float2*)(Cz + (size_t)(row0 + 8) * ldc + col) = v1;
        }
    }
}

// ---------------------------------------------------------------- combine biases + scale + mask + XSoftmax
__global__ void softmax_kernel() {
    __shared__ float red[256];
    int zq = blockIdx.x;
    int z = zq >> 9, q = zq & 511;
    int bb = z / NHEAD;
    int tid = threadIdx.x;
    const float SCALE = sqrtf(192.0f);  // sqrt(D*3)
    float mq = g_maskf[bb * SEQ + q];
    size_t rowS = ((size_t)z * SEQ + q) * SEQ;
    size_t rowC = ((size_t)z * SEQ + q) * RSPAN;

    int k0 = tid, k1 = tid + 256;
    float s0 = g_scores[rowS + k0]
             + g_c2p[rowC + g_c2pidx[q * SEQ + k0]]
             + g_p2c[((size_t)z * SEQ + k0) * RSPAN + g_p2cidx[k0 * SEQ + q]];
    float s1 = g_scores[rowS + k1]
             + g_c2p[rowC + g_c2pidx[q * SEQ + k1]]
             + g_p2c[((size_t)z * SEQ + k1) * RSPAN + g_p2cidx[k1 * SEQ + q]];
    s0 /= SCALE; s1 /= SCALE;
    bool m0 = (mq * g_maskf[bb * SEQ + k0]) > 0.f;
    bool m1 = (mq * g_maskf[bb * SEQ + k1]) > 0.f;
    float v0 = m0 ? s0 : -FLT_MAX;
    float v1 = m1 ? s1 : -FLT_MAX;

    red[tid] = fmaxf(v0, v1); __syncthreads();
    for (int s = 128; s; s >>= 1) { if (tid < s) red[tid] = fmaxf(red[tid], red[tid + s]); __syncthreads(); }
    float mx = red[0]; __syncthreads();

    float p0 = m0 ? expf(v0 - mx) : 0.f;
    float p1 = m1 ? expf(v1 - mx) : 0.f;
    red[tid] = p0 + p1; __syncthreads();
    for (int s = 128; s; s >>= 1) { if (tid < s) red[tid] += red[tid + s]; __syncthreads(); }
    float sum = red[0];
    float inv = (sum > 0.f) ? (1.0f / sum) : 0.f;
    g_scores[rowS + k0] = p0 * inv;
    g_scores[rowS + k1] = p1 * inv;
}

// ---------------------------------------------------------------- decoder + per-token NLL
__global__ void decoder_kernel(const float* __restrict__ tin, const float* __restrict__ Wd,
                               const float* __restrict__ bd, const int* __restrict__ labels,
                               float* __restrict__ out, int out_size) {
    __shared__ float sm[HID];
    __shared__ float red[256];
    __shared__ float lg[NCLS];
    int t = blockIdx.x, tid = threadIdx.x;
    for (int i = tid; i < HID; i += 256) sm[i] = tin[(size_t)t * HID + i];
    __syncthreads();
    for (int c = 0; c < NCLS; c++) {
        float p = 0.f;
        for (int k = tid; k < HID; k += 256) p += sm[k] * Wd[(size_t)k * NCLS + c];
        red[tid] = p; __syncthreads();
        for (int s = 128; s; s >>= 1) { if (tid < s) red[tid] += red[tid + s]; __syncthreads(); }
        if (tid == 0) lg[c] = red[0] + bd[c];
        __syncthreads();
    }
    if (out_size >= TOK * NCLS && tid < NCLS) out[(size_t)t * NCLS + tid] = lg[tid];
    if (tid == 0) {
        float mx = -FLT_MAX;
        for (int c = 0; c < NCLS; c++) mx = fmaxf(mx, lg[c]);
        float se = 0.f;
        for (int c = 0; c < NCLS; c++) se += expf(lg[c] - mx);
        float lse = mx + logf(se);
        g_nll[t] = (lse - lg[labels[t]]) * g_maskf[t];
    }
}

// ---------------------------------------------------------------- final deterministic loss reduce
__global__ void loss_kernel(float* __restrict__ out, int out_size) {
    __shared__ float rn[256], rd[256];
    int tid = threadIdx.x;
    float a = 0.f, d = 0.f;
    for (int t = tid; t < TOK; t += 256) { a += g_nll[t]; d += g_maskf[t]; }
    rn[tid] = a; rd[tid] = d; __syncthreads();
    for (int s = 128; s; s >>= 1) {
        if (tid < s) { rn[tid] += rn[tid + s]; rd[tid] += rd[tid + s]; }
        __syncthreads();
    }
    if (tid == 0) {
        float loss = rn[0] / fmaxf(rd[0], 1.0f);
        if (out_size > TOK * NCLS) out[TOK * NCLS] = loss;
        else if (out_size == 1)    out[0] = loss;
    }
}

// ---------------------------------------------------------------- launch
extern "C" void kernel_launch(void* const* d_in, const int* in_sizes, int n_in,
                              void* d_out, int out_size) {
    const float* word_emb = (const float*)d_in[0];
    const float* emb_ln_s = (const float*)d_in[1];
    const float* emb_ln_b = (const float*)d_in[2];
    const float* rel_emb  = (const float*)d_in[3];
    const float* rel_ln_s = (const float*)d_in[4];
    const float* rel_ln_b = (const float*)d_in[5];
    const float* Wq = (const float*)d_in[6];   const float* bq = (const float*)d_in[7];
    const float* Wk = (const float*)d_in[8];   const float* bk = (const float*)d_in[9];
    const float* Wv = (const float*)d_in[10];  const float* bv = (const float*)d_in[11];
    const float* Wo = (const float*)d_in[12];  const float* bo = (const float*)d_in[13];
    const float* ln1_s = (const float*)d_in[14]; const float* ln1_b = (const float*)d_in[15];
    const float* W1 = (const float*)d_in[16];  const float* b1 = (const float*)d_in[17];
    const float* W2 = (const float*)d_in[18];  const float* b2 = (const float*)d_in[19];
    const float* ln2_s = (const float*)d_in[20]; const float* ln2_b = (const float*)d_in[21];
    const float* Wt = (const float*)d_in[22];  const float* bt = (const float*)d_in[23];
    const float* tln_s = (const float*)d_in[24]; const float* tln_b = (const float*)d_in[25];
    const float* Wd = (const float*)d_in[26];  const float* bd = (const float*)d_in[27];
    const int* ids    = (const int*)d_in[28];
    const int* att    = (const int*)d_in[29];
    const int* labels = (const int*)d_in[30];
    float* out = (float*)d_out;
    (void)in_sizes; (void)n_in;

    cudaFuncSetAttribute(gemm_tc<1,0>, cudaFuncAttributeMaxDynamicSharedMemorySize, SMEM_BYTES);
    cudaFuncSetAttribute(gemm_tc<0,0>, cudaFuncAttributeMaxDynamicSharedMemorySize, SMEM_BYTES);
    cudaFuncSetAttribute(gemm_tc<1,1>, cudaFuncAttributeMaxDynamicSharedMemorySize, SMEM_BYTES);

    float *x, *qbuf, *ctx, *tmp, *relln, *qkv, *pos, *wcatT, *bcat;
    float *woT, *w1T, *w2T, *wtT, *vt, *scores, *c2p, *p2c, *ff;
    cudaGetSymbolAddress((void**)&x, g_x);       cudaGetSymbolAddress((void**)&qbuf, g_q);
    cudaGetSymbolAddress((void**)&ctx, g_ctx);   cudaGetSymbolAddress((void**)&tmp, g_tmp);
    cudaGetSymbolAddress((void**)&relln, g_relln);
    cudaGetSymbolAddress((void**)&qkv, g_qkv);   cudaGetSymbolAddress((void**)&pos, g_pos);
    cudaGetSymbolAddress((void**)&wcatT, g_wcatT); cudaGetSymbolAddress((void**)&bcat, g_bcat);
    cudaGetSymbolAddress((void**)&woT, g_woT);   cudaGetSymbolAddress((void**)&w1T, g_w1T);
    cudaGetSymbolAddress((void**)&w2T, g_w2T);   cudaGetSymbolAddress((void**)&wtT, g_wtT);
    cudaGetSymbolAddress((void**)&vt, g_vt);
    cudaGetSymbolAddress((void**)&scores, g_scores);
    cudaGetSymbolAddress((void**)&c2p, g_c2p);   cudaGetSymbolAddress((void**)&p2c, g_p2c);
    cudaGetSymbolAddress((void**)&ff, g_ff);

    embed_kernel<<<TOK, 256>>>(word_emb, emb_ln_s, emb_ln_b, ids, att);
    relidx_kernel<<<(SEQ * SEQ + 255) / 256, 256>>>();
    ln_kernel<<<RSPAN, 256>>>(rel_emb, rel_ln_s, rel_ln_b, relln);
    transpose_kernel<<<dim3(HID / 32, HID / 32), dim3(32, 8)>>>(wtT, Wt, HID, HID);

    const long SH3 = (long)SEQ * 3 * HID;
    const long SS  = (long)SEQ * SEQ;
    const long SR  = (long)SEQ * RSPAN;
    dim3 tb(32, 8);

    for (int l = 0; l < NLAYER; l++) {
        const float* wo = Wo + (size_t)l * HID * HID;  const float* bol = bo + (size_t)l * HID;
        const float* w1 = W1 + (size_t)l * HID * FFD;  const float* b1l = b1 + (size_t)l * FFD;
        const float* w2 = W2 + (size_t)l * FFD * HID;  const float* b2l = b2 + (size_t)l * HID;

        transpose_kernel<<<dim3(HID / 32, HID / 32), tb>>>(wcatT,                 Wq + (size_t)l * HID * HID, HID, HID);
        transpose_kernel<<<dim3(HID / 32, HID / 32), tb>>>(wcatT + HID * HID,     Wk + (size_t)l * HID * HID, HID, HID);
        transpose_kernel<<<dim3(HID / 32, HID / 32), tb>>>(wcatT + 2 * HID * HID, Wv + (size_t)l * HID * HID, HID, HID);
        transpose_kernel<<<dim3(HID / 32, HID / 32), tb>>>(woT, wo, HID, HID);
        transpose_kernel<<<dim3(FFD / 32, HID / 32), tb>>>(w1T, w1, HID, FFD);
        transpose_kernel<<<dim3(HID / 32, FFD / 32), tb>>>(w2T, w2, FFD, HID);
        bcat_kernel<<<12, 256>>>(bq + (size_t)l * HID, bk + (size_t)l * HID, bv + (size_t)l * HID);

        // fused QKV: [1024,1024] @ [3072,1024]^T
        gemm_tc<1, 0><<<dim3(3 * HID / BN, TOK / BM, 1), 256, SMEM_BYTES>>>(
            x, wcatT, bcat, qkv, HID, HID, HID, 3 * HID, 0, 0, 0, 0, 0, 0);
        // fused pos_q|pos_k: [512,1024] @ [2048,1024]^T
        gemm_tc<1, 0><<<dim3(2 * HID / BN, RSPAN / BM, 1), 256, SMEM_BYTES>>>(
            relln, wcatT, bcat, pos, HID, HID, HID, 2 * HID, 0, 0, 0, 0, 0, 0);

        vtrans_kernel<<<dim3(SEQ / 32, HDIM / 32, ZBATCH), tb>>>(qkv, vt);

        // scores[b,h,q,k] = q.k
        gemm_tc<0, 0><<<dim3(SEQ / BN, SEQ / BM, ZBATCH), 256, SMEM_BYTES>>>(
            qkv, qkv + HID, nullptr, scores, HDIM, 3 * HID, 3 * HID, SEQ,
            SH3, (long)HDIM, SH3, (long)HDIM, (long)NHEAD * SS, SS);
        // c2p[b,h,q,r] = q.posk[r]
        gemm_tc<0, 0><<<dim3(RSPAN / BN, SEQ / BM, ZBATCH), 256, SMEM_BYTES>>>(
            qkv, pos + HID, nullptr, c2p, HDIM, 3 * HID, 2 * HID, RSPAN,
            SH3, (long)HDIM, 0L, (long)HDIM, (long)NHEAD * SR, SR);
        // p2c[b,h,k,r] = k.posq[r]
        gemm_tc<0, 0><<<dim3(RSPAN / BN, SEQ / BM, ZBATCH), 256, SMEM_BYTES>>>(
            qkv + HID, pos, nullptr, p2c, HDIM, 3 * HID, 2 * HID, RSPAN,
            SH3, (long)HDIM, 0L, (long)HDIM, (long)NHEAD * SR, SR);

        softmax_kernel<<<ZBATCH * SEQ, 256>>>();

        // ctx = probs @ vt^T  (NT, K=512)
        gemm_tc<0, 0><<<dim3(HDIM / BN, SEQ / BM, ZBATCH), 256, SMEM_BYTES>>>(
            scores, vt, nullptr, ctx, SEQ, SEQ, SEQ, HID,
            (long)NHEAD * SS, SS, (long)NHEAD * HDIM * SEQ, (long)HDIM * SEQ,
            (long)SEQ * HID, (long)HDIM);

        gemm_tc<1, 0><<<dim3(HID / BN, TOK / BM, 1), 256, SMEM_BYTES>>>(
            ctx, woT, bol, tmp, HID, HID, HID, HID, 0, 0, 0, 0, 0, 0);
        add_ln_kernel<<<TOK, 256>>>(x, tmp, ln1_s + (size_t)l * HID, ln1_b + (size_t)l * HID, x);

        gemm_tc<1, 1><<<dim3(FFD / BN, TOK / BM, 1), 256, SMEM_BYTES>>>(
            x, w1T, b1l, ff, HID, HID, HID, FFD, 0, 0, 0, 0, 0, 0);
        gemm_tc<1, 0><<<dim3(HID / BN, TOK / BM, 1), 256, SMEM_BYTES>>>(
            ff, w2T, b2l, tmp, FFD, FFD, FFD, HID, 0, 0, 0, 0, 0, 0);
        add_ln_kernel<<<TOK, 256>>>(x, tmp, ln2_s + (size_t)l * HID, ln2_b + (size_t)l * HID, x);
    }

    // transform head: LN(gelu(x @ Wt + bt))
    gemm_tc<1, 1><<<dim3(HID / BN, TOK / BM, 1), 256, SMEM_BYTES>>>(
        x, wtT, bt, tmp, HID, HID, HID, HID, 0, 0, 0, 0, 0, 0);
    ln_kernel<<<TOK, 256>>>(tmp, tln_s, tln_b, qbuf);

    decoder_kernel<<<TOK, 256>>>(qbuf, Wd, bd, labels, out, out_size);
    loss_kernel<<<1, 256>>>(out, out_size);
}